// round 2
// baseline (speedup 1.0000x reference)
#include <cuda_runtime.h>

#define B_  8
#define N_  8192
#define M_  2048
#define C1_ 128
#define C2_ 256
#define H_  256
#define KTOT (C1_ + C2_)

// ---------------- scratch (no allocation allowed) ----------------
__device__ int   g_idx[B_ * N_ * 3];
__device__ float g_w[B_ * N_ * 3];
__device__ float g_feat[(size_t)B_ * C2_ * N_];  // interpolated features (B,256,N)
__device__ float g_h[(size_t)B_ * H_ * N_];      // hidden layer (B,256,N)

// ---------------- 3-NN: per (b,n) find 3 nearest known points ----------------
__global__ __launch_bounds__(256) void knn_kernel(const float* __restrict__ unknown,
                                                  const float* __restrict__ known) {
    __shared__ float kx[M_], ky[M_], kz[M_];
    const int b = blockIdx.y;
    const float* kb = known + (size_t)b * M_ * 3;
    for (int i = threadIdx.x; i < M_; i += 256) {
        kx[i] = kb[3 * i + 0];
        ky[i] = kb[3 * i + 1];
        kz[i] = kb[3 * i + 2];
    }
    __syncthreads();

    const int n = blockIdx.x * 256 + threadIdx.x;
    const float* u = unknown + ((size_t)b * N_ + n) * 3;
    const float ux = u[0], uy = u[1], uz = u[2];

    float d0 = 3.4e38f, d1 = 3.4e38f, d2 = 3.4e38f;
    int i0 = 0, i1 = 0, i2 = 0;
    for (int m = 0; m < M_; ++m) {
        const float dx = ux - kx[m];
        const float dy = uy - ky[m];
        const float dz = uz - kz[m];
        const float d = fmaf(dx, dx, fmaf(dy, dy, dz * dz));
        if (d < d2) {  // strict '<' keeps earliest index on ties, matching top_k
            if (d < d1) {
                if (d < d0) { d2 = d1; i2 = i1; d1 = d0; i1 = i0; d0 = d; i0 = m; }
                else        { d2 = d1; i2 = i1; d1 = d;  i1 = m; }
            } else          { d2 = d;  i2 = m; }
        }
    }
    const float s0 = sqrtf(fmaxf(d0, 0.f));
    const float s1 = sqrtf(fmaxf(d1, 0.f));
    const float s2 = sqrtf(fmaxf(d2, 0.f));
    const float r0 = 1.f / (s0 + 1e-8f);
    const float r1 = 1.f / (s1 + 1e-8f);
    const float r2 = 1.f / (s2 + 1e-8f);
    const float inv = 1.f / (r0 + r1 + r2);
    const size_t o = ((size_t)b * N_ + n) * 3;
    g_idx[o] = i0; g_idx[o + 1] = i1; g_idx[o + 2] = i2;
    g_w[o] = r0 * inv; g_w[o + 1] = r1 * inv; g_w[o + 2] = r2 * inv;
}

// ------------- interpolation: smem-stage known_feats rows, gather from smem -------------
#define CCH 4  // channels per block (4 * 2048 * 4B = 32KB smem)
__global__ __launch_bounds__(256) void interp_kernel(const float* __restrict__ kf) {
    __shared__ float s[CCH][M_];
    const int b = blockIdx.y;
    const int c0 = blockIdx.x * CCH;
    const float* base = kf + ((size_t)b * C2_ + c0) * M_;
    for (int i = threadIdx.x; i < CCH * M_; i += 256)
        s[i >> 11][i & (M_ - 1)] = base[i];
    __syncthreads();

    for (int n = threadIdx.x; n < N_; n += 256) {
        const size_t o = ((size_t)b * N_ + n) * 3;
        const int i0 = g_idx[o], i1 = g_idx[o + 1], i2 = g_idx[o + 2];
        const float w0 = g_w[o], w1 = g_w[o + 1], w2 = g_w[o + 2];
        float* op = g_feat + ((size_t)b * C2_ + c0) * N_ + n;
#pragma unroll
        for (int c = 0; c < CCH; ++c) {
            op[(size_t)c * N_] = fmaf(w0, s[c][i0], fmaf(w1, s[c][i1], w2 * s[c][i2]));
        }
    }
}

// ------------- SGEMM + bias + ReLU: out[b] = relu(W @ X[b] + bias) -------------
// W: (H, K) row-major.  X rows selected per-channel:
//   mode 0 (layer 1): c < 256 -> g_feat[b], else unknow_feats[b] (concat, no copy)
//   mode 1 (layer 2): g_h[b]
// 128x128x16 tile, 256 threads, 8x8 micro-tile, double-buffered smem.
__global__ __launch_bounds__(256) void gemm_relu_kernel(
    const float* __restrict__ W, const float* __restrict__ bias,
    const float* __restrict__ X1, float* __restrict__ out_param,
    int K, int mode) {
    __shared__ float Ws[2][16][128];
    __shared__ float Xs[2][16][128];

    const int tid = threadIdx.x;
    const int b = blockIdx.z;
    const int m0 = blockIdx.y * 128;
    const int n0 = blockIdx.x * 128;
    const int tx = tid & 15;
    const int ty = tid >> 4;

    float4 wreg[2], xreg[2];

    auto x_rowptr = [&](int c) -> const float* {
        if (mode == 0) {
            if (c < C2_) return g_feat + ((size_t)b * C2_ + c) * N_;
            return X1 + ((size_t)b * C1_ + (c - C2_)) * N_;
        }
        return g_h + ((size_t)b * H_ + c) * N_;
    };

    auto prefetch = [&](int k0) {
#pragma unroll
        for (int i = 0; i < 2; ++i) {
            const int f = tid + i * 256;        // 512 float4s of W tile
            const int r = f >> 2, c4 = f & 3;   // row in [0,128), col4 in [0,4)
            wreg[i] = *(const float4*)(W + (size_t)(m0 + r) * K + k0 + c4 * 4);
        }
#pragma unroll
        for (int i = 0; i < 2; ++i) {
            const int f = tid + i * 256;        // 512 float4s of X tile
            const int kr = f >> 5, nc4 = f & 31;
            xreg[i] = *(const float4*)(x_rowptr(k0 + kr) + n0 + nc4 * 4);
        }
    };

    auto stage = [&](int buf) {
#pragma unroll
        for (int i = 0; i < 2; ++i) {
            const int f = tid + i * 256;
            const int r = f >> 2, c4 = f & 3;
            Ws[buf][c4 * 4 + 0][r] = wreg[i].x;
            Ws[buf][c4 * 4 + 1][r] = wreg[i].y;
            Ws[buf][c4 * 4 + 2][r] = wreg[i].z;
            Ws[buf][c4 * 4 + 3][r] = wreg[i].w;
        }
#pragma unroll
        for (int i = 0; i < 2; ++i) {
            const int f = tid + i * 256;
            const int kr = f >> 5, nc4 = f & 31;
            *(float4*)&Xs[buf][kr][nc4 * 4] = xreg[i];
        }
    };

    float acc[8][8];
#pragma unroll
    for (int i = 0; i < 8; ++i)
#pragma unroll
        for (int j = 0; j < 8; ++j) acc[i][j] = 0.f;

    prefetch(0);
    stage(0);
    __syncthreads();

    const int T = K >> 4;
    int buf = 0;
    for (int t = 0; t < T; ++t) {
        if (t + 1 < T) prefetch((t + 1) << 4);
#pragma unroll
        for (int kk = 0; kk < 16; ++kk) {
            float a[8], bb[8];
            *(float4*)(a)      = *(const float4*)&Ws[buf][kk][ty * 8];
            *(float4*)(a + 4)  = *(const float4*)&Ws[buf][kk][ty * 8 + 4];
            *(float4*)(bb)     = *(const float4*)&Xs[buf][kk][tx * 8];
            *(float4*)(bb + 4) = *(const float4*)&Xs[buf][kk][tx * 8 + 4];
#pragma unroll
            for (int i = 0; i < 8; ++i)
#pragma unroll
                for (int j = 0; j < 8; ++j)
                    acc[i][j] = fmaf(a[i], bb[j], acc[i][j]);
        }
        if (t + 1 < T) {
            stage(buf ^ 1);
            __syncthreads();
            buf ^= 1;
        }
    }

    float* out = (mode == 0) ? (g_h + (size_t)b * H_ * N_)
                             : (out_param + (size_t)b * H_ * N_);
#pragma unroll
    for (int i = 0; i < 8; ++i) {
        const int m = m0 + ty * 8 + i;
        const float bi = bias[m];
        float4 v0, v1;
        v0.x = fmaxf(acc[i][0] + bi, 0.f);
        v0.y = fmaxf(acc[i][1] + bi, 0.f);
        v0.z = fmaxf(acc[i][2] + bi, 0.f);
        v0.w = fmaxf(acc[i][3] + bi, 0.f);
        v1.x = fmaxf(acc[i][4] + bi, 0.f);
        v1.y = fmaxf(acc[i][5] + bi, 0.f);
        v1.z = fmaxf(acc[i][6] + bi, 0.f);
        v1.w = fmaxf(acc[i][7] + bi, 0.f);
        *(float4*)(out + (size_t)m * N_ + n0 + tx * 8)     = v0;
        *(float4*)(out + (size_t)m * N_ + n0 + tx * 8 + 4) = v1;
    }
}

// ---------------- launch ----------------
extern "C" void kernel_launch(void* const* d_in, const int* in_sizes, int n_in,
                              void* d_out, int out_size) {
    const float* unknown      = (const float*)d_in[0];  // (B, N, 3)
    const float* known        = (const float*)d_in[1];  // (B, M, 3)
    const float* unknow_feats = (const float*)d_in[2];  // (B, C1, N)
    const float* known_feats  = (const float*)d_in[3];  // (B, C2, M)
    const float* W1           = (const float*)d_in[4];  // (H, C1+C2)
    const float* b1           = (const float*)d_in[5];  // (H)
    const float* W2           = (const float*)d_in[6];  // (H, H)
    const float* b2           = (const float*)d_in[7];  // (H)
    float* out = (float*)d_out;                         // (B, H, N)

    knn_kernel<<<dim3(N_ / 256, B_), 256>>>(unknown, known);
    interp_kernel<<<dim3(C2_ / CCH, B_), 256>>>(known_feats);
    gemm_relu_kernel<<<dim3(N_ / 128, H_ / 128, B_), 256>>>(W1, b1, unknow_feats,
                                                            nullptr, KTOT, 0);
    gemm_relu_kernel<<<dim3(N_ / 128, H_ / 128, B_), 256>>>(W2, b2, nullptr,
                                                            out, H_, 1);
}

// round 6
// speedup vs baseline: 1.5057x; 1.5057x over previous
#include <cuda_runtime.h>
#include <cuda_bf16.h>
#include <cstdint>

#define B_  8
#define N_  8192
#define M_  2048
#define C1_ 128
#define C2_ 256
#define H_  256
#define KTOT (C1_ + C2_)

// ---------------- scratch (no allocation allowed) ----------------
__device__ int   g_idx[B_ * N_ * 3];
__device__ float g_w[B_ * N_ * 3];
__device__ float g_feat[(size_t)B_ * C2_ * N_];            // interpolated (B,256,N) fp32
__device__ __nv_bfloat16 g_w1h[H_ * KTOT];
__device__ __nv_bfloat16 g_w1l[H_ * KTOT];
__device__ __nv_bfloat16 g_w2h[H_ * H_];
__device__ __nv_bfloat16 g_w2l[H_ * H_];
__device__ __nv_bfloat16 g_xt1h[(size_t)B_ * N_ * KTOT];   // X1^T (B, N, 384) hi
__device__ __nv_bfloat16 g_xt1l[(size_t)B_ * N_ * KTOT];
__device__ __nv_bfloat16 g_xt2h[(size_t)B_ * N_ * H_];     // h^T (B, N, 256) hi
__device__ __nv_bfloat16 g_xt2l[(size_t)B_ * N_ * H_];

// ---------------- small helpers ----------------
__device__ __forceinline__ uint32_t smem_u32(const void* p) {
    uint32_t a;
    asm("{ .reg .u64 t; cvta.to.shared.u64 t, %1; cvt.u32.u64 %0, t; }" : "=r"(a) : "l"(p));
    return a;
}
__device__ __forceinline__ void cp16(uint32_t dst, const void* src) {
    asm volatile("cp.async.cg.shared.global [%0], [%1], 16;" :: "r"(dst), "l"(src));
}
#define CP_COMMIT() asm volatile("cp.async.commit_group;" ::: "memory")
#define CP_WAIT0()  asm volatile("cp.async.wait_group 0;" ::: "memory")

__device__ __forceinline__ void ldm_x4(uint32_t* r, uint32_t a) {
    asm volatile("ldmatrix.sync.aligned.m8n8.x4.shared.b16 {%0,%1,%2,%3}, [%4];"
                 : "=r"(r[0]), "=r"(r[1]), "=r"(r[2]), "=r"(r[3]) : "r"(a));
}
__device__ __forceinline__ void ldm_x2(uint32_t* r, uint32_t a) {
    asm volatile("ldmatrix.sync.aligned.m8n8.x2.shared.b16 {%0,%1}, [%2];"
                 : "=r"(r[0]), "=r"(r[1]) : "r"(a));
}
__device__ __forceinline__ void mma_bf16(float* c, const uint32_t* a, const uint32_t* b) {
    asm volatile(
        "mma.sync.aligned.m16n8k16.row.col.f32.bf16.bf16.f32 "
        "{%0,%1,%2,%3}, {%4,%5,%6,%7}, {%8,%9}, {%0,%1,%2,%3};"
        : "+f"(c[0]), "+f"(c[1]), "+f"(c[2]), "+f"(c[3])
        : "r"(a[0]), "r"(a[1]), "r"(a[2]), "r"(a[3]), "r"(b[0]), "r"(b[1]));
}
__device__ __forceinline__ void split_bf16(float v, __nv_bfloat16& hi, __nv_bfloat16& lo) {
    hi = __float2bfloat16_rn(v);
    lo = __float2bfloat16_rn(v - __bfloat162float(hi));
}

// ---------------- 3-NN ----------------
__global__ __launch_bounds__(256) void knn_kernel(const float* __restrict__ unknown,
                                                  const float* __restrict__ known) {
    __shared__ float kx[M_], ky[M_], kz[M_];
    const int b = blockIdx.y;
    const float* kb = known + (size_t)b * M_ * 3;
    for (int i = threadIdx.x; i < M_; i += 256) {
        kx[i] = kb[3 * i + 0];
        ky[i] = kb[3 * i + 1];
        kz[i] = kb[3 * i + 2];
    }
    __syncthreads();

    const int n = blockIdx.x * 256 + threadIdx.x;
    const float* u = unknown + ((size_t)b * N_ + n) * 3;
    const float ux = u[0], uy = u[1], uz = u[2];

    float d0 = 3.4e38f, d1 = 3.4e38f, d2 = 3.4e38f;
    int i0 = 0, i1 = 0, i2 = 0;
#pragma unroll 4
    for (int m = 0; m < M_; ++m) {
        const float dx = ux - kx[m];
        const float dy = uy - ky[m];
        const float dz = uz - kz[m];
        const float d = fmaf(dx, dx, fmaf(dy, dy, dz * dz));
        if (d < d2) {
            if (d < d1) {
                if (d < d0) { d2 = d1; i2 = i1; d1 = d0; i1 = i0; d0 = d; i0 = m; }
                else        { d2 = d1; i2 = i1; d1 = d;  i1 = m; }
            } else          { d2 = d;  i2 = m; }
        }
    }
    const float s0 = sqrtf(fmaxf(d0, 0.f));
    const float s1 = sqrtf(fmaxf(d1, 0.f));
    const float s2 = sqrtf(fmaxf(d2, 0.f));
    const float r0 = 1.f / (s0 + 1e-8f);
    const float r1 = 1.f / (s1 + 1e-8f);
    const float r2 = 1.f / (s2 + 1e-8f);
    const float inv = 1.f / (r0 + r1 + r2);
    const size_t o = ((size_t)b * N_ + n) * 3;
    g_idx[o] = i0; g_idx[o + 1] = i1; g_idx[o + 2] = i2;
    g_w[o] = r0 * inv; g_w[o + 1] = r1 * inv; g_w[o + 2] = r2 * inv;
}

// ---------------- interpolation -> g_feat (B, C2, N) fp32 ----------------
#define CCH 4
__global__ __launch_bounds__(256) void interp_kernel(const float* __restrict__ kf) {
    __shared__ float s[CCH][M_];
    const int b = blockIdx.y;
    const int c0 = blockIdx.x * CCH;
    const float* base = kf + ((size_t)b * C2_ + c0) * M_;
    for (int i = threadIdx.x; i < CCH * M_; i += 256)
        s[i >> 11][i & (M_ - 1)] = base[i];
    __syncthreads();

    for (int n = threadIdx.x; n < N_; n += 256) {
        const size_t o = ((size_t)b * N_ + n) * 3;
        const int i0 = g_idx[o], i1 = g_idx[o + 1], i2 = g_idx[o + 2];
        const float w0 = g_w[o], w1 = g_w[o + 1], w2 = g_w[o + 2];
        float* op = g_feat + ((size_t)b * C2_ + c0) * N_ + n;
#pragma unroll
        for (int c = 0; c < CCH; ++c)
            op[(size_t)c * N_] = fmaf(w0, s[c][i0], fmaf(w1, s[c][i1], w2 * s[c][i2]));
    }
}

// ---------------- W -> bf16 hi/lo ----------------
__global__ __launch_bounds__(256) void wconv_kernel(const float* __restrict__ W1,
                                                    const float* __restrict__ W2) {
    const int i = blockIdx.x * 256 + threadIdx.x;
    if (i < H_ * KTOT) { __nv_bfloat16 h, l; split_bf16(W1[i], h, l); g_w1h[i] = h; g_w1l[i] = l; }
    if (i < H_ * H_)   { __nv_bfloat16 h, l; split_bf16(W2[i], h, l); g_w2h[i] = h; g_w2l[i] = l; }
}

// ------- transpose+convert: [g_feat ; unknow_feats] (K,N) fp32 -> XT1 (N,K) bf16 hi/lo -------
__global__ __launch_bounds__(256) void xt1_kernel(const float* __restrict__ uf) {
    __shared__ float s[64][65];
    const int b = blockIdx.z;
    const int k0 = blockIdx.y * 64;
    const int n0 = blockIdx.x * 64;
    for (int i = threadIdx.x; i < 64 * 64; i += 256) {
        const int r = i >> 6, c = i & 63;
        const int k = k0 + r;
        const float* src = (k < C2_) ? (g_feat + ((size_t)b * C2_ + k) * N_)
                                     : (uf + ((size_t)b * C1_ + (k - C2_)) * N_);
        s[r][c] = src[n0 + c];
    }
    __syncthreads();

    const int q = threadIdx.x & 3;       // k quarter (16 wide)
    const int nl = threadIdx.x >> 2;     // local n (0..63)
    union { uint4 v[2]; __nv_bfloat16 h[16]; } Hh, Ll;
#pragma unroll
    for (int i = 0; i < 16; ++i) {
        __nv_bfloat16 h, l;
        split_bf16(s[q * 16 + i][nl], h, l);
        Hh.h[i] = h; Ll.h[i] = l;
    }
    const size_t base = ((size_t)b * N_ + n0 + nl) * KTOT + k0 + q * 16;
    *(uint4*)(g_xt1h + base) = Hh.v[0];
    *(uint4*)(g_xt1h + base + 8) = Hh.v[1];
    *(uint4*)(g_xt1l + base) = Ll.v[0];
    *(uint4*)(g_xt1l + base + 8) = Ll.v[1];
}

// ======== bf16x3 HMMA GEMM:  D(128x128) = W[m0:,:K] @ XT[n0:,:K]^T, +bias, ReLU ========
// All W/X operands are __device__ globals selected INSIDE the kernel by `mode`
// (device symbols must never be passed as host-side launch args — on GB300 the
// host shadow address is ATS-accessible and silently reads host memory).
#define KC   32
#define RSB  80                       // padded row stride bytes (40 bf16)
#define MATB (128 * RSB)              // 10240 B per matrix
#define STGB (4 * MATB)               // 40960 B per stage
#define GSM  (2 * STGB)               // 81920 B dynamic smem

__global__ __launch_bounds__(256)
void mma_gemm_kernel(const float* __restrict__ bias, float* __restrict__ out,
                     int K, int mode) {
    extern __shared__ char smem[];
    const uint32_t sbase = smem_u32(smem);
    const int tid = threadIdx.x;
    const int wid = tid >> 5;
    const int lane = tid & 31;
    const int b = blockIdx.z;
    const int m0 = blockIdx.y * 128;
    const int n0 = blockIdx.x * 128;

    const __nv_bfloat16 *Wh, *Wl, *xb_h, *xb_l;
    if (mode == 0) {
        Wh = g_w1h; Wl = g_w1l;
        xb_h = g_xt1h + (size_t)b * N_ * KTOT;
        xb_l = g_xt1l + (size_t)b * N_ * KTOT;
    } else {
        Wh = g_w2h; Wl = g_w2l;
        xb_h = g_xt2h + (size_t)b * N_ * H_;
        xb_l = g_xt2l + (size_t)b * N_ * H_;
    }

    // issue one k-chunk (KC cols) of all 4 matrices into stage s
    auto issue = [&](int k0c, int s) {
        const uint32_t dbase = sbase + s * STGB;
#pragma unroll
        for (int i = 0; i < 8; ++i) {
            const int idx = tid + i * 256;          // 0..2047
            const int mat = idx >> 9;
            const int r = (idx >> 2) & 127;
            const int c = idx & 3;                  // 16B chunk (8 bf16)
            const uint32_t dst = dbase + mat * MATB + r * RSB + c * 16;
            const __nv_bfloat16* src;
            if (mat == 0)      src = Wh   + (size_t)(m0 + r) * K + k0c + c * 8;
            else if (mat == 1) src = Wl   + (size_t)(m0 + r) * K + k0c + c * 8;
            else if (mat == 2) src = xb_h + (size_t)(n0 + r) * K + k0c + c * 8;
            else               src = xb_l + (size_t)(n0 + r) * K + k0c + c * 8;
            cp16(dst, src);
        }
    };

    const int wm = wid >> 2;            // 0..1  -> m offset
    const int wn = wid & 3;             // 0..3  -> n offset
    const int m_off = wm * 64;
    const int n_off = wn * 32;

    float acc[4][4][4];
#pragma unroll
    for (int i = 0; i < 4; ++i)
#pragma unroll
        for (int j = 0; j < 4; ++j)
#pragma unroll
            for (int q = 0; q < 4; ++q) acc[i][j][q] = 0.f;

    const int T = K / KC;
    issue(0, 0);
    CP_COMMIT();
    int buf = 0;

    for (int t = 0; t < T; ++t) {
        CP_WAIT0();
        __syncthreads();
        if (t + 1 < T) { issue((t + 1) * KC, buf ^ 1); CP_COMMIT(); }

        const uint32_t ah_b = sbase + buf * STGB;
        const uint32_t al_b = ah_b + MATB;
        const uint32_t bh_b = ah_b + 2 * MATB;
        const uint32_t bl_b = ah_b + 3 * MATB;

#pragma unroll
        for (int k16 = 0; k16 < 2; ++k16) {
            const int kbyte = k16 * 32;
            uint32_t Ah[4][4], Al[4][4], Bh[4][2], Bl[4][2];
            // B fragments (x2): lanes 0-15 supply addresses
            const int brow = (lane & 7);
            const int bcol = ((lane >> 3) & 1) * 16;
#pragma unroll
            for (int nt = 0; nt < 4; ++nt) {
                const uint32_t off = (uint32_t)(n_off + nt * 8 + brow) * RSB + kbyte + bcol;
                ldm_x2(Bh[nt], bh_b + off);
                ldm_x2(Bl[nt], bl_b + off);
            }
            // A fragments (x4)
            const int arow = (lane & 15);
            const int acol = (lane >> 4) * 16;
#pragma unroll
            for (int mt = 0; mt < 4; ++mt) {
                const uint32_t off = (uint32_t)(m_off + mt * 16 + arow) * RSB + kbyte + acol;
                ldm_x4(Ah[mt], ah_b + off);
                ldm_x4(Al[mt], al_b + off);
            }
            // 3 combos, interleaved so each acc is revisited every 16 MMAs
#pragma unroll
            for (int mt = 0; mt < 4; ++mt)
#pragma unroll
                for (int nt = 0; nt < 4; ++nt) mma_bf16(acc[mt][nt], Ah[mt], Bh[nt]);
#pragma unroll
            for (int mt = 0; mt < 4; ++mt)
#pragma unroll
                for (int nt = 0; nt < 4; ++nt) mma_bf16(acc[mt][nt], Ah[mt], Bl[nt]);
#pragma unroll
            for (int mt = 0; mt < 4; ++mt)
#pragma unroll
                for (int nt = 0; nt < 4; ++nt) mma_bf16(acc[mt][nt], Al[mt], Bh[nt]);
        }
        __syncthreads();
        buf ^= 1;
    }

    // ---------------- epilogue ----------------
    if (mode == 1) {
        // final layer: out[b][m][n] = relu(acc + bias), fp32
#pragma unroll
        for (int mt = 0; mt < 4; ++mt) {
            const int r0 = m0 + m_off + mt * 16 + (lane >> 2);
            const float bi0 = bias[r0];
            const float bi1 = bias[r0 + 8];
#pragma unroll
            for (int nt = 0; nt < 4; ++nt) {
                const int cc = n0 + n_off + nt * 8 + (lane & 3) * 2;
                float2 v0, v1;
                v0.x = fmaxf(acc[mt][nt][0] + bi0, 0.f);
                v0.y = fmaxf(acc[mt][nt][1] + bi0, 0.f);
                v1.x = fmaxf(acc[mt][nt][2] + bi1, 0.f);
                v1.y = fmaxf(acc[mt][nt][3] + bi1, 0.f);
                *(float2*)(out + ((size_t)b * H_ + r0) * N_ + cc) = v0;
                *(float2*)(out + ((size_t)b * H_ + r0 + 8) * N_ + cc) = v1;
            }
        }
    } else {
        // hidden layer: relu(acc + bias) -> transpose via smem -> XT2 (b, n, m) bf16 hi/lo
        float* f = (float*)smem;                      // 128 x 129 fp32 tile
#pragma unroll
        for (int mt = 0; mt < 4; ++mt) {
            const int rl0 = m_off + mt * 16 + (lane >> 2);
            const float bi0 = bias[m0 + rl0];
            const float bi1 = bias[m0 + rl0 + 8];
#pragma unroll
            for (int nt = 0; nt < 4; ++nt) {
                const int cl = n_off + nt * 8 + (lane & 3) * 2;
                f[rl0 * 129 + cl]           = fmaxf(acc[mt][nt][0] + bi0, 0.f);
                f[rl0 * 129 + cl + 1]       = fmaxf(acc[mt][nt][1] + bi0, 0.f);
                f[(rl0 + 8) * 129 + cl]     = fmaxf(acc[mt][nt][2] + bi1, 0.f);
                f[(rl0 + 8) * 129 + cl + 1] = fmaxf(acc[mt][nt][3] + bi1, 0.f);
            }
        }
        __syncthreads();
        const int n = tid >> 1;           // 0..127
        const int half = tid & 1;         // m half: 0..63 or 64..127
        union { uint4 v[8]; __nv_bfloat16 h[64]; } Hh, Ll;
#pragma unroll
        for (int i = 0; i < 64; ++i) {
            __nv_bfloat16 h, l;
            split_bf16(f[(half * 64 + i) * 129 + n], h, l);
            Hh.h[i] = h; Ll.h[i] = l;
        }
        const size_t base = ((size_t)b * N_ + n0 + n) * H_ + m0 + half * 64;
#pragma unroll
        for (int i = 0; i < 8; ++i) {
            *(uint4*)(g_xt2h + base + 8 * i) = Hh.v[i];
            *(uint4*)(g_xt2l + base + 8 * i) = Ll.v[i];
        }
    }
}

// ---------------- launch ----------------
extern "C" void kernel_launch(void* const* d_in, const int* in_sizes, int n_in,
                              void* d_out, int out_size) {
    const float* unknown      = (const float*)d_in[0];  // (B, N, 3)
    const float* known        = (const float*)d_in[1];  // (B, M, 3)
    const float* unknow_feats = (const float*)d_in[2];  // (B, C1, N)
    const float* known_feats  = (const float*)d_in[3];  // (B, C2, M)
    const float* W1           = (const float*)d_in[4];  // (H, C1+C2)
    const float* b1           = (const float*)d_in[5];  // (H)
    const float* W2           = (const float*)d_in[6];  // (H, H)
    const float* b2           = (const float*)d_in[7];  // (H)
    float* out = (float*)d_out;                         // (B, H, N)

    cudaFuncSetAttribute(mma_gemm_kernel, cudaFuncAttributeMaxDynamicSharedMemorySize, GSM);

    knn_kernel<<<dim3(N_ / 256, B_), 256>>>(unknown, known);
    interp_kernel<<<dim3(C2_ / CCH, B_), 256>>>(known_feats);
    wconv_kernel<<<(H_ * KTOT + 255) / 256, 256>>>(W1, W2);
    xt1_kernel<<<dim3(N_ / 64, KTOT / 64, B_), 256>>>(unknow_feats);

    // layer 1: hidden = relu(W1 @ [interp; unknow] + b1) -> XT2 (transposed bf16 hi/lo)
    mma_gemm_kernel<<<dim3(N_ / 128, 2, B_), 256, GSM>>>(b1, nullptr, KTOT, 0);
    // layer 2: out = relu(W2 @ hidden + b2), fp32
    mma_gemm_kernel<<<dim3(N_ / 128, 2, B_), 256, GSM>>>(b2, out, H_, 1);
}

// round 7
// speedup vs baseline: 1.7447x; 1.1587x over previous
#include <cuda_runtime.h>
#include <cuda_bf16.h>
#include <cstdint>

#define B_  8
#define N_  8192
#define M_  2048
#define C1_ 128
#define C2_ 256
#define H_  256
#define KTOT (C1_ + C2_)

// ---------------- scratch (no allocation allowed) ----------------
__device__ int   g_idx[B_ * N_ * 3];
__device__ float g_w[B_ * N_ * 3];
__device__ float g_feat[(size_t)B_ * C2_ * N_];        // interpolated (B,256,N) fp32 (k-major)
__device__ __nv_bfloat16 g_w1h[H_ * KTOT];
__device__ __nv_bfloat16 g_w1l[H_ * KTOT];
__device__ __nv_bfloat16 g_w2h[H_ * H_];
__device__ __nv_bfloat16 g_w2l[H_ * H_];
__device__ __nv_bfloat16 g_hh[(size_t)B_ * H_ * N_];   // hidden (b, m, n) bf16 hi
__device__ __nv_bfloat16 g_hl[(size_t)B_ * H_ * N_];   // hidden lo

// ---------------- small helpers ----------------
__device__ __forceinline__ uint32_t smem_u32(const void* p) {
    uint32_t a;
    asm("{ .reg .u64 t; cvta.to.shared.u64 t, %1; cvt.u32.u64 %0, t; }" : "=r"(a) : "l"(p));
    return a;
}
__device__ __forceinline__ void cp16(uint32_t dst, const void* src) {
    asm volatile("cp.async.cg.shared.global [%0], [%1], 16;" :: "r"(dst), "l"(src));
}
#define CP_COMMIT() asm volatile("cp.async.commit_group;" ::: "memory")
#define CP_WAIT0()  asm volatile("cp.async.wait_group 0;" ::: "memory")

__device__ __forceinline__ void ldm_x4(uint32_t* r, uint32_t a) {
    asm volatile("ldmatrix.sync.aligned.m8n8.x4.shared.b16 {%0,%1,%2,%3}, [%4];"
                 : "=r"(r[0]), "=r"(r[1]), "=r"(r[2]), "=r"(r[3]) : "r"(a));
}
__device__ __forceinline__ void ldm_x2t(uint32_t* r, uint32_t a) {
    asm volatile("ldmatrix.sync.aligned.m8n8.x2.trans.shared.b16 {%0,%1}, [%2];"
                 : "=r"(r[0]), "=r"(r[1]) : "r"(a));
}
__device__ __forceinline__ void mma_bf16(float* c, const uint32_t* a, const uint32_t* b) {
    asm volatile(
        "mma.sync.aligned.m16n8k16.row.col.f32.bf16.bf16.f32 "
        "{%0,%1,%2,%3}, {%4,%5,%6,%7}, {%8,%9}, {%0,%1,%2,%3};"
        : "+f"(c[0]), "+f"(c[1]), "+f"(c[2]), "+f"(c[3])
        : "r"(a[0]), "r"(a[1]), "r"(a[2]), "r"(a[3]), "r"(b[0]), "r"(b[1]));
}
__device__ __forceinline__ void split_bf16(float v, __nv_bfloat16& hi, __nv_bfloat16& lo) {
    hi = __float2bfloat16_rn(v);
    lo = __float2bfloat16_rn(v - __bfloat162float(hi));
}
__device__ __forceinline__ uint32_t pack2(__nv_bfloat16 a, __nv_bfloat16 b) {
    __nv_bfloat162 p(a, b);
    return *(uint32_t*)&p;
}

// ---------------- 3-NN ----------------
__global__ __launch_bounds__(256) void knn_kernel(const float* __restrict__ unknown,
                                                  const float* __restrict__ known) {
    __shared__ float kx[M_], ky[M_], kz[M_];
    const int b = blockIdx.y;
    const float* kb = known + (size_t)b * M_ * 3;
    for (int i = threadIdx.x; i < M_; i += 256) {
        kx[i] = kb[3 * i + 0];
        ky[i] = kb[3 * i + 1];
        kz[i] = kb[3 * i + 2];
    }
    __syncthreads();

    const int n = blockIdx.x * 256 + threadIdx.x;
    const float* u = unknown + ((size_t)b * N_ + n) * 3;
    const float ux = u[0], uy = u[1], uz = u[2];

    float d0 = 3.4e38f, d1 = 3.4e38f, d2 = 3.4e38f;
    int i0 = 0, i1 = 0, i2 = 0;
#pragma unroll 4
    for (int m = 0; m < M_; ++m) {
        const float dx = ux - kx[m];
        const float dy = uy - ky[m];
        const float dz = uz - kz[m];
        const float d = fmaf(dx, dx, fmaf(dy, dy, dz * dz));
        if (d < d2) {
            if (d < d1) {
                if (d < d0) { d2 = d1; i2 = i1; d1 = d0; i1 = i0; d0 = d; i0 = m; }
                else        { d2 = d1; i2 = i1; d1 = d;  i1 = m; }
            } else          { d2 = d;  i2 = m; }
        }
    }
    const float s0 = sqrtf(fmaxf(d0, 0.f));
    const float s1 = sqrtf(fmaxf(d1, 0.f));
    const float s2 = sqrtf(fmaxf(d2, 0.f));
    const float r0 = 1.f / (s0 + 1e-8f);
    const float r1 = 1.f / (s1 + 1e-8f);
    const float r2 = 1.f / (s2 + 1e-8f);
    const float inv = 1.f / (r0 + r1 + r2);
    const size_t o = ((size_t)b * N_ + n) * 3;
    g_idx[o] = i0; g_idx[o + 1] = i1; g_idx[o + 2] = i2;
    g_w[o] = r0 * inv; g_w[o + 1] = r1 * inv; g_w[o + 2] = r2 * inv;
}

// ---------------- interpolation -> g_feat (B, C2, N) fp32 ----------------
#define CCH 4
__global__ __launch_bounds__(256) void interp_kernel(const float* __restrict__ kf) {
    __shared__ float s[CCH][M_];
    const int b = blockIdx.y;
    const int c0 = blockIdx.x * CCH;
    const float* base = kf + ((size_t)b * C2_ + c0) * M_;
    for (int i = threadIdx.x; i < CCH * M_; i += 256)
        s[i >> 11][i & (M_ - 1)] = base[i];
    __syncthreads();

    for (int n = threadIdx.x; n < N_; n += 256) {
        const size_t o = ((size_t)b * N_ + n) * 3;
        const int i0 = g_idx[o], i1 = g_idx[o + 1], i2 = g_idx[o + 2];
        const float w0 = g_w[o], w1 = g_w[o + 1], w2 = g_w[o + 2];
        float* op = g_feat + ((size_t)b * C2_ + c0) * N_ + n;
#pragma unroll
        for (int c = 0; c < CCH; ++c)
            op[(size_t)c * N_] = fmaf(w0, s[c][i0], fmaf(w1, s[c][i1], w2 * s[c][i2]));
    }
}

// ---------------- W -> bf16 hi/lo ----------------
__global__ __launch_bounds__(256) void wconv_kernel(const float* __restrict__ W1,
                                                    const float* __restrict__ W2) {
    const int i = blockIdx.x * 256 + threadIdx.x;
    if (i < H_ * KTOT) { __nv_bfloat16 h, l; split_bf16(W1[i], h, l); g_w1h[i] = h; g_w1l[i] = l; }
    if (i < H_ * H_)   { __nv_bfloat16 h, l; split_bf16(W2[i], h, l); g_w2h[i] = h; g_w2l[i] = l; }
}

// ======== bf16x3 HMMA GEMM, B operand consumed k-major via ldmatrix.trans ========
// mode 0: X = concat[g_feat ; unknow_feats] fp32 (k-major), converted to bf16 hi/lo
//         in-kernel; output -> g_hh/g_hl (b, m, n) bf16 hi/lo, +bias, ReLU.
// mode 1: X = g_hh/g_hl bf16 (k-major, no conversion); output -> fp32 out, +bias, ReLU.
// Device-global operands are selected INSIDE the kernel (never passed as host args).
#define KC    32
#define RSB   80                      // A row stride bytes (32 bf16 + pad)
#define A_MAT 10240                   // 128 * RSB
#define BROW  272                     // B row stride bytes (128 bf16 + 16 pad)
#define B_MAT 8704                    // 32 * BROW
#define OFF_AH 0
#define OFF_AL 10240
#define OFF_BH 20480
#define OFF_BL 29184
#define OFF_BF 37888                  // fp32 staging (mode 0): 32 rows * 512B
#define STG    54272
#define GSM    (2 * STG)              // 108544 B dynamic smem

__global__ __launch_bounds__(256)
void mma_gemm_kernel(const float* __restrict__ uf, const float* __restrict__ bias,
                     float* __restrict__ out, int K, int mode) {
    extern __shared__ char smem[];
    const uint32_t sbase = smem_u32(smem);
    const int tid = threadIdx.x;
    const int wid = tid >> 5;
    const int lane = tid & 31;
    const int b = blockIdx.z;
    const int m0 = blockIdx.y * 128;
    const int n0 = blockIdx.x * 128;

    const __nv_bfloat16* Wh = (mode == 0) ? g_w1h : g_w2h;
    const __nv_bfloat16* Wl = (mode == 0) ? g_w1l : g_w2l;

    // fp32 X row for mode 0 (concat: first C2 channels interpolated, then unknow_feats)
    auto xrow = [&](int c) -> const float* {
        if (c < C2_) return g_feat + ((size_t)b * C2_ + c) * N_;
        return uf + ((size_t)b * C1_ + (c - C2_)) * N_;
    };

    auto issue = [&](int k0c, int s) {
        const uint32_t dbase = sbase + s * STG;
        // A: hi/lo weights, m-major rows of 32 bf16 (64B) -> 1024 cp16
#pragma unroll
        for (int i = 0; i < 4; ++i) {
            const int idx = tid + i * 256;
            const int mat = idx >> 9;
            const int r = (idx >> 2) & 127;
            const int c = idx & 3;
            const uint32_t dst = dbase + (mat ? OFF_AL : OFF_AH) + r * RSB + c * 16;
            const __nv_bfloat16* src = (mat ? Wl : Wh) + (size_t)(m0 + r) * K + k0c + c * 8;
            cp16(dst, src);
        }
        if (mode == 0) {
            // B fp32: 32 k-rows x 128 n fp32 (512B/row) -> 1024 cp16
#pragma unroll
            for (int i = 0; i < 4; ++i) {
                const int idx = tid + i * 256;
                const int r = idx >> 5;
                const int c = idx & 31;
                cp16(dbase + OFF_BF + r * 512 + c * 16, xrow(k0c + r) + n0 + c * 4);
            }
        } else {
            // B bf16 hi/lo direct: 32 k-rows x 128 n bf16 (256B/row) -> 1024 cp16
#pragma unroll
            for (int i = 0; i < 4; ++i) {
                const int idx = tid + i * 256;
                const int mat = idx >> 9;
                const int r = (idx >> 4) & 31;
                const int c = idx & 15;
                const uint32_t dst = dbase + (mat ? OFF_BL : OFF_BH) + r * BROW + c * 16;
                const __nv_bfloat16* src = (mat ? g_hl : g_hh)
                    + ((size_t)b * H_ + k0c + r) * N_ + n0 + c * 8;
                cp16(dst, src);
            }
        }
    };

    const int wm = wid >> 2;            // 0..1  -> m offset
    const int wn = wid & 3;             // 0..3  -> n offset
    const int m_off = wm * 64;
    const int n_off = wn * 32;

    float acc[4][4][4];
#pragma unroll
    for (int i = 0; i < 4; ++i)
#pragma unroll
        for (int j = 0; j < 4; ++j)
#pragma unroll
            for (int q = 0; q < 4; ++q) acc[i][j][q] = 0.f;

    const int T = K / KC;
    issue(0, 0);
    CP_COMMIT();
    int buf = 0;

    for (int t = 0; t < T; ++t) {
        CP_WAIT0();
        __syncthreads();
        if (t + 1 < T) { issue((t + 1) * KC, buf ^ 1); CP_COMMIT(); }

        const uint32_t dbase = sbase + buf * STG;
        if (mode == 0) {
            // convert fp32 -> bf16 hi/lo, layout-preserving (k-major)
            const int r = tid >> 3;
            const int c0 = (tid & 7) * 16;
            const float* sf = (const float*)(smem + (size_t)buf * STG + OFF_BF + r * 512) + c0;
            union { uint4 v[2]; __nv_bfloat16 h[16]; } Hh, Ll;
#pragma unroll
            for (int i = 0; i < 16; ++i) {
                __nv_bfloat16 h, l;
                split_bf16(sf[i], h, l);
                Hh.h[i] = h; Ll.h[i] = l;
            }
            char* bh = smem + (size_t)buf * STG + OFF_BH + r * BROW + c0 * 2;
            char* bl = smem + (size_t)buf * STG + OFF_BL + r * BROW + c0 * 2;
            *(uint4*)bh = Hh.v[0]; *(uint4*)(bh + 16) = Hh.v[1];
            *(uint4*)bl = Ll.v[0]; *(uint4*)(bl + 16) = Ll.v[1];
            __syncthreads();
        }

        const uint32_t ah_b = dbase + OFF_AH;
        const uint32_t al_b = dbase + OFF_AL;
        const uint32_t bh_b = dbase + OFF_BH;
        const uint32_t bl_b = dbase + OFF_BL;

#pragma unroll
        for (int k16 = 0; k16 < 2; ++k16) {
            uint32_t Ah[4][4], Al[4][4], Bh[4][2], Bl[4][2];
            // B fragments via trans-ldmatrix from k-major rows
            const int krow = k16 * 16 + (lane & 15);
#pragma unroll
            for (int nt = 0; nt < 4; ++nt) {
                const uint32_t off = (uint32_t)krow * BROW + (n_off + nt * 8) * 2;
                ldm_x2t(Bh[nt], bh_b + off);
                ldm_x2t(Bl[nt], bl_b + off);
            }
            // A fragments (m-major, as before)
            const int arow = (lane & 15);
            const int acol = (lane >> 4) * 16 + k16 * 32;
#pragma unroll
            for (int mt = 0; mt < 4; ++mt) {
                const uint32_t off = (uint32_t)(m_off + mt * 16 + arow) * RSB + acol;
                ldm_x4(Ah[mt], ah_b + off);
                ldm_x4(Al[mt], al_b + off);
            }
            // 3 combos (Ah*Bh + Ah*Bl + Al*Bh)
#pragma unroll
            for (int mt = 0; mt < 4; ++mt)
#pragma unroll
                for (int nt = 0; nt < 4; ++nt) mma_bf16(acc[mt][nt], Ah[mt], Bh[nt]);
#pragma unroll
            for (int mt = 0; mt < 4; ++mt)
#pragma unroll
                for (int nt = 0; nt < 4; ++nt) mma_bf16(acc[mt][nt], Ah[mt], Bl[nt]);
#pragma unroll
            for (int mt = 0; mt < 4; ++mt)
#pragma unroll
                for (int nt = 0; nt < 4; ++nt) mma_bf16(acc[mt][nt], Al[mt], Bh[nt]);
        }
        __syncthreads();
        buf ^= 1;
    }

    // ---------------- epilogue ----------------
    if (mode == 1) {
        // final layer: out[b][m][n] = relu(acc + bias), fp32
#pragma unroll
        for (int mt = 0; mt < 4; ++mt) {
            const int r0 = m0 + m_off + mt * 16 + (lane >> 2);
            const float bi0 = bias[r0];
            const float bi1 = bias[r0 + 8];
#pragma unroll
            for (int nt = 0; nt < 4; ++nt) {
                const int cc = n0 + n_off + nt * 8 + (lane & 3) * 2;
                float2 v0, v1;
                v0.x = fmaxf(acc[mt][nt][0] + bi0, 0.f);
                v0.y = fmaxf(acc[mt][nt][1] + bi0, 0.f);
                v1.x = fmaxf(acc[mt][nt][2] + bi1, 0.f);
                v1.y = fmaxf(acc[mt][nt][3] + bi1, 0.f);
                *(float2*)(out + ((size_t)b * H_ + r0) * N_ + cc) = v0;
                *(float2*)(out + ((size_t)b * H_ + r0 + 8) * N_ + cc) = v1;
            }
        }
    } else {
        // hidden layer: relu(acc + bias) -> g_hh/g_hl (b, m, n) bf16 hi/lo, straight
        // from accumulators (layout already k-major for GEMM2's trans-ldmatrix).
#pragma unroll
        for (int mt = 0; mt < 4; ++mt) {
            const int r0 = m0 + m_off + mt * 16 + (lane >> 2);
            const float bi0 = bias[r0];
            const float bi1 = bias[r0 + 8];
#pragma unroll
            for (int nt = 0; nt < 4; ++nt) {
                const int cc = n0 + n_off + nt * 8 + (lane & 3) * 2;
                const float v0 = fmaxf(acc[mt][nt][0] + bi0, 0.f);
                const float v1 = fmaxf(acc[mt][nt][1] + bi0, 0.f);
                const float v2 = fmaxf(acc[mt][nt][2] + bi1, 0.f);
                const float v3 = fmaxf(acc[mt][nt][3] + bi1, 0.f);
                __nv_bfloat16 h0, l0, h1, l1, h2, l2, h3, l3;
                split_bf16(v0, h0, l0); split_bf16(v1, h1, l1);
                split_bf16(v2, h2, l2); split_bf16(v3, h3, l3);
                const size_t i0 = ((size_t)b * H_ + r0) * N_ + cc;
                const size_t i1 = ((size_t)b * H_ + r0 + 8) * N_ + cc;
                *(uint32_t*)(g_hh + i0) = pack2(h0, h1);
                *(uint32_t*)(g_hl + i0) = pack2(l0, l1);
                *(uint32_t*)(g_hh + i1) = pack2(h2, h3);
                *(uint32_t*)(g_hl + i1) = pack2(l2, l3);
            }
        }
    }
}

// ---------------- launch ----------------
extern "C" void kernel_launch(void* const* d_in, const int* in_sizes, int n_in,
                              void* d_out, int out_size) {
    const float* unknown      = (const float*)d_in[0];  // (B, N, 3)
    const float* known        = (const float*)d_in[1];  // (B, M, 3)
    const float* unknow_feats = (const float*)d_in[2];  // (B, C1, N)
    const float* known_feats  = (const float*)d_in[3];  // (B, C2, M)
    const float* W1           = (const float*)d_in[4];  // (H, C1+C2)
    const float* b1           = (const float*)d_in[5];  // (H)
    const float* W2           = (const float*)d_in[6];  // (H, H)
    const float* b2           = (const float*)d_in[7];  // (H)
    float* out = (float*)d_out;                         // (B, H, N)

    cudaFuncSetAttribute(mma_gemm_kernel, cudaFuncAttributeMaxDynamicSharedMemorySize, GSM);

    knn_kernel<<<dim3(N_ / 256, B_), 256>>>(unknown, known);
    interp_kernel<<<dim3(C2_ / CCH, B_), 256>>>(known_feats);
    wconv_kernel<<<(H_ * KTOT + 255) / 256, 256>>>(W1, W2);

    // layer 1: hidden = relu(W1 @ [interp; unknow] + b1) -> g_hh/g_hl (bf16 hi/lo)
    mma_gemm_kernel<<<dim3(N_ / 128, 2, B_), 256, GSM>>>(unknow_feats, b1, nullptr, KTOT, 0);
    // layer 2: out = relu(W2 @ hidden + b2), fp32
    mma_gemm_kernel<<<dim3(N_ / 128, 2, B_), 256, GSM>>>(nullptr, b2, out, H_, 1);
}